// round 1
// baseline (speedup 1.0000x reference)
#include <cuda_runtime.h>
#include <math.h>

#define TT   512
#define BB   64
#define II   1024
#define HH   1024
#define G4   4096   // 4*H

// Scratch: x_gates [T, B, 4H] fp32 (536 MB, bss — static device array, no runtime alloc)
__device__ float g_xg[(size_t)TT * BB * G4];
// c ping-pong buffers
__device__ float g_c[2 * BB * HH];

// ---------------------------------------------------------------------------
// Phase 1: x_gates[m, n] = sum_k input[m,k] * w_ih[n,k] + b_ih[n] + b_hh[n]
// M = T*B = 32768, N = 4096, K = 1024.  BM=BN=64, BK=16, 4x4 microtile.
// ---------------------------------------------------------------------------
__global__ __launch_bounds__(256)
void gemm_xgates(const float* __restrict__ A,    // [M, K]
                 const float* __restrict__ W,    // [N, K]
                 const float* __restrict__ bih,
                 const float* __restrict__ bhh,
                 float* __restrict__ C)          // [M, N]
{
    __shared__ float As[16][64];   // [k][m]
    __shared__ float Bs[16][64];   // [k][n]

    const int tx = threadIdx.x, ty = threadIdx.y;     // 16 x 16
    const int tid = ty * 16 + tx;
    const int m0 = blockIdx.y * 64;
    const int n0 = blockIdx.x * 64;

    const int lr = tid >> 2;   // 0..63
    const int lc = tid & 3;    // 0..3  (float4 column)

    const float* Arow = A + (size_t)(m0 + lr) * II + lc * 4;
    const float* Wrow = W + (size_t)(n0 + lr) * II + lc * 4;

    float acc[4][4] = {};

    for (int k0 = 0; k0 < II; k0 += 16) {
        float4 av = *(const float4*)(Arow + k0);
        float4 bv = *(const float4*)(Wrow + k0);
        As[lc * 4 + 0][lr] = av.x; As[lc * 4 + 1][lr] = av.y;
        As[lc * 4 + 2][lr] = av.z; As[lc * 4 + 3][lr] = av.w;
        Bs[lc * 4 + 0][lr] = bv.x; Bs[lc * 4 + 1][lr] = bv.y;
        Bs[lc * 4 + 2][lr] = bv.z; Bs[lc * 4 + 3][lr] = bv.w;
        __syncthreads();

        #pragma unroll
        for (int kk = 0; kk < 16; kk++) {
            float4 a = *(const float4*)&As[kk][ty * 4];
            float4 b = *(const float4*)&Bs[kk][tx * 4];
            acc[0][0] += a.x * b.x; acc[0][1] += a.x * b.y; acc[0][2] += a.x * b.z; acc[0][3] += a.x * b.w;
            acc[1][0] += a.y * b.x; acc[1][1] += a.y * b.y; acc[1][2] += a.y * b.z; acc[1][3] += a.y * b.w;
            acc[2][0] += a.z * b.x; acc[2][1] += a.z * b.y; acc[2][2] += a.z * b.z; acc[2][3] += a.z * b.w;
            acc[3][0] += a.w * b.x; acc[3][1] += a.w * b.y; acc[3][2] += a.w * b.z; acc[3][3] += a.w * b.w;
        }
        __syncthreads();
    }

    #pragma unroll
    for (int i = 0; i < 4; i++) {
        const int m = m0 + ty * 4 + i;
        #pragma unroll
        for (int j = 0; j < 4; j++) {
            const int n = n0 + tx * 4 + j;
            C[(size_t)m * G4 + n] = acc[i][j] + bih[n] + bhh[n];
        }
    }
}

// ---------------------------------------------------------------------------
// Phase 2: one timestep. 128 CTAs; CTA nb owns h-columns [nb*8, nb*8+8) and
// computes the 4 matching gate sections for all 64 batches, then fuses the
// LSTM pointwise update. gates = xg[t] + h_in @ w_hh^T
// ---------------------------------------------------------------------------
__global__ __launch_bounds__(256)
void lstm_step(const float* __restrict__ xg,    // [B, 4H] slice for t
               const float* __restrict__ h_in,  // [B, H]
               const float* __restrict__ c_in,  // [B, H]
               const float* __restrict__ Whh,   // [4H, H]
               float* __restrict__ h_out,       // [B, H] (into d_out)
               float* __restrict__ c_out)       // [B, H]
{
    __shared__ float Hs[32][64];   // [k][b]
    __shared__ float Ws[32][32];   // [k][local gate col]
    __shared__ float Gb[64][33];   // staged gates, padded

    const int tx = threadIdx.x, ty = threadIdx.y;   // 16 x 16
    const int tid = ty * 16 + tx;
    const int nb = blockIdx.x;                      // 0..127

    // W load mapping: local col j -> global gate row g
    const int wj = tid >> 3;                        // 0..31
    const int wc = tid & 7;                         // 0..7 (float4 col)
    const int wg = (wj >> 3) * HH + nb * 8 + (wj & 7);
    const float* wrow = Whh + (size_t)wg * HH + wc * 4;

    float acc[4][2] = {};

    for (int k0 = 0; k0 < HH; k0 += 32) {
        #pragma unroll
        for (int r = 0; r < 2; r++) {
            const int id = tid + r * 256;
            const int b  = id >> 3;
            const int c4 = id & 7;
            float4 v = *(const float4*)(h_in + (size_t)b * HH + k0 + c4 * 4);
            Hs[c4 * 4 + 0][b] = v.x; Hs[c4 * 4 + 1][b] = v.y;
            Hs[c4 * 4 + 2][b] = v.z; Hs[c4 * 4 + 3][b] = v.w;
        }
        {
            float4 v = *(const float4*)(wrow + k0);
            Ws[wc * 4 + 0][wj] = v.x; Ws[wc * 4 + 1][wj] = v.y;
            Ws[wc * 4 + 2][wj] = v.z; Ws[wc * 4 + 3][wj] = v.w;
        }
        __syncthreads();

        #pragma unroll
        for (int kk = 0; kk < 32; kk++) {
            float4 a = *(const float4*)&Hs[kk][ty * 4];
            float2 b = *(const float2*)&Ws[kk][tx * 2];
            acc[0][0] += a.x * b.x; acc[0][1] += a.x * b.y;
            acc[1][0] += a.y * b.x; acc[1][1] += a.y * b.y;
            acc[2][0] += a.z * b.x; acc[2][1] += a.z * b.y;
            acc[3][0] += a.w * b.x; acc[3][1] += a.w * b.y;
        }
        __syncthreads();
    }

    // add x_gates, stage to shared for cross-thread i/f/g/o gather
    #pragma unroll
    for (int i = 0; i < 4; i++) {
        const int b = ty * 4 + i;
        #pragma unroll
        for (int j = 0; j < 2; j++) {
            const int col  = tx * 2 + j;                          // 0..31
            const int gcol = (col >> 3) * HH + nb * 8 + (col & 7);
            Gb[b][col] = acc[i][j] + xg[(size_t)b * G4 + gcol];
        }
    }
    __syncthreads();

    // pointwise LSTM update: 64 batches x 8 h-cols = 512 elems, 2 per thread
    #pragma unroll
    for (int r = 0; r < 2; r++) {
        const int e  = tid + r * 256;
        const int b  = e >> 3;
        const int hh = e & 7;
        const float ig = Gb[b][hh];
        const float fg = Gb[b][8 + hh];
        const float gg = Gb[b][16 + hh];
        const float og = Gb[b][24 + hh];
        const int hcol = nb * 8 + hh;

        const float c_old = c_in[(size_t)b * HH + hcol];
        const float si = 1.0f / (1.0f + expf(-ig));
        const float sf = 1.0f / (1.0f + expf(-fg));
        const float so = 1.0f / (1.0f + expf(-og));
        const float tg = tanhf(gg);
        const float cn = sf * c_old + si * tg;
        const float hn = so * tanhf(cn);

        c_out[(size_t)b * HH + hcol] = cn;
        h_out[(size_t)b * HH + hcol] = hn;
    }
}

// ---------------------------------------------------------------------------
__global__ void final_copy(const float* __restrict__ hl, const float* __restrict__ cl,
                           float* __restrict__ hf, float* __restrict__ cf)
{
    int i = blockIdx.x * blockDim.x + threadIdx.x;
    const int stride = gridDim.x * blockDim.x;
    for (; i < BB * HH; i += stride) {
        hf[i] = hl[i];
        cf[i] = cl[i];
    }
}

// ---------------------------------------------------------------------------
extern "C" void kernel_launch(void* const* d_in, const int* in_sizes, int n_in,
                              void* d_out, int out_size)
{
    const float* input = (const float*)d_in[0];   // [T, B, I]
    const float* h0    = (const float*)d_in[1];   // [B, H]
    const float* c0    = (const float*)d_in[2];   // [B, H]
    const float* w_ih  = (const float*)d_in[3];   // [4H, I]
    const float* w_hh  = (const float*)d_in[4];   // [4H, H]
    const float* b_ih  = (const float*)d_in[5];   // [4H]
    const float* b_hh  = (const float*)d_in[6];   // [4H]

    float* outputs = (float*)d_out;                    // [T, B, H]
    float* hf = outputs + (size_t)TT * BB * HH;        // [B, H]
    float* cf = hf + (size_t)BB * HH;                  // [B, H]

    float* xg = nullptr;
    float* cbuf = nullptr;
    cudaGetSymbolAddress((void**)&xg, g_xg);
    cudaGetSymbolAddress((void**)&cbuf, g_c);

    dim3 blk(16, 16);

    // Phase 1: big input-projection GEMM
    gemm_xgates<<<dim3(G4 / 64, (TT * BB) / 64), blk>>>(input, w_ih, b_ih, b_hh, xg);

    // Phase 2: 512 sequential steps; h chained through d_out itself
    for (int t = 0; t < TT; t++) {
        const float* h_in = (t == 0) ? h0 : outputs + (size_t)(t - 1) * BB * HH;
        const float* c_in = (t == 0) ? c0 : cbuf + (size_t)((t - 1) & 1) * BB * HH;
        float* c_o = cbuf + (size_t)(t & 1) * BB * HH;
        lstm_step<<<128, blk>>>(xg + (size_t)t * BB * G4, h_in, c_in, w_hh,
                                outputs + (size_t)t * BB * HH, c_o);
    }

    // Tail: h_f, c_f
    final_copy<<<128, 512>>>(outputs + (size_t)(TT - 1) * BB * HH,
                             cbuf + (size_t)((TT - 1) & 1) * BB * HH, hf, cf);
}

// round 3
// speedup vs baseline: 1.3586x; 1.3586x over previous
#include <cuda_runtime.h>
#include <math.h>

#define TT   512
#define BB   64
#define II   1024
#define HH   1024
#define G4   4096      // 4*H
#define GRID 128       // persistent CTAs (<= 148 SMs, all co-resident)

typedef unsigned long long ull;

// Scratch: x_gates [T, B, 4H] fp32 (static device array; no runtime alloc)
__device__ float g_xg[(size_t)TT * BB * G4];
__device__ unsigned g_bar;

__device__ __forceinline__ ull pack2(float x) {
    ull r; asm("mov.b64 %0, {%1,%1};" : "=l"(r) : "f"(x)); return r;
}
__device__ __forceinline__ void fma2(ull& d, ull a, ull b) {
    asm("fma.rn.f32x2 %0, %1, %2, %3;" : "=l"(d) : "l"(a), "l"(b), "l"(d));
}
__device__ __forceinline__ float2 unpack2(ull v) {
    float2 r; asm("mov.b64 {%0,%1}, %2;" : "=f"(r.x), "=f"(r.y) : "l"(v)); return r;
}

// ---------------------------------------------------------------------------
// Phase 1: x_gates = input @ w_ih^T + b_ih + b_hh
// ---------------------------------------------------------------------------
__global__ __launch_bounds__(256)
void gemm_xgates(const float* __restrict__ A, const float* __restrict__ W,
                 const float* __restrict__ bih, const float* __restrict__ bhh,
                 float* __restrict__ C)
{
    __shared__ float As[16][64];
    __shared__ float Bs[16][64];

    const int tx = threadIdx.x, ty = threadIdx.y;
    const int tid = ty * 16 + tx;
    const int m0 = blockIdx.y * 64;
    const int n0 = blockIdx.x * 64;
    const int lr = tid >> 2;
    const int lc = tid & 3;

    const float* Arow = A + (size_t)(m0 + lr) * II + lc * 4;
    const float* Wrow = W + (size_t)(n0 + lr) * II + lc * 4;

    float acc[4][4] = {};

    for (int k0 = 0; k0 < II; k0 += 16) {
        float4 av = *(const float4*)(Arow + k0);
        float4 bv = *(const float4*)(Wrow + k0);
        As[lc * 4 + 0][lr] = av.x; As[lc * 4 + 1][lr] = av.y;
        As[lc * 4 + 2][lr] = av.z; As[lc * 4 + 3][lr] = av.w;
        Bs[lc * 4 + 0][lr] = bv.x; Bs[lc * 4 + 1][lr] = bv.y;
        Bs[lc * 4 + 2][lr] = bv.z; Bs[lc * 4 + 3][lr] = bv.w;
        __syncthreads();
        #pragma unroll
        for (int kk = 0; kk < 16; kk++) {
            float4 a = *(const float4*)&As[kk][ty * 4];
            float4 b = *(const float4*)&Bs[kk][tx * 4];
            acc[0][0] += a.x * b.x; acc[0][1] += a.x * b.y; acc[0][2] += a.x * b.z; acc[0][3] += a.x * b.w;
            acc[1][0] += a.y * b.x; acc[1][1] += a.y * b.y; acc[1][2] += a.y * b.z; acc[1][3] += a.y * b.w;
            acc[2][0] += a.z * b.x; acc[2][1] += a.z * b.y; acc[2][2] += a.z * b.z; acc[2][3] += a.z * b.w;
            acc[3][0] += a.w * b.x; acc[3][1] += a.w * b.y; acc[3][2] += a.w * b.z; acc[3][3] += a.w * b.w;
        }
        __syncthreads();
    }

    #pragma unroll
    for (int i = 0; i < 4; i++) {
        const int m = m0 + ty * 4 + i;
        #pragma unroll
        for (int j = 0; j < 4; j++) {
            const int n = n0 + tx * 4 + j;
            C[(size_t)m * G4 + n] = acc[i][j] + bih[n] + bhh[n];
        }
    }
}

// ---------------------------------------------------------------------------
__global__ void bar_reset() { g_bar = 0; }

// ---------------------------------------------------------------------------
// Persistent recurrence kernel: 128 CTAs x 256 threads run all 512 steps.
// CTA nb owns h-cols [nb*8, nb*8+8) -> 32 gate rows; its W slice (128 KB)
// stays in SMEM. Split-K by 2 (two 128-thread groups), 4x4 microtile with
// fma.rn.f32x2. Register-prefetch pipeline hides L2/DRAM staging latency
// under the fma loop. c lives in SMEM. Grid sync via atomic counter.
// ---------------------------------------------------------------------------
#define WS_OFF 0
#define HS_OFF 32768
#define HS_G   (64 * 68)
#define GP_OFF (HS_OFF + 2 * HS_G)
#define GB_OFF (GP_OFF + 64 * 33)
#define CS_OFF (GB_OFF + 64 * 33)
#define SMEM_FLOATS (CS_OFF + 512)

__global__ __launch_bounds__(256, 1)
void lstm_persist(const float* __restrict__ xg,   // [T, B, 4H]
                  const float* h0, const float* c0,
                  const float* __restrict__ Whh,  // [4H, H]
                  float* out,                      // [T, B, H]
                  float* hf, float* cf)            // [B, H] each
{
    extern __shared__ float sm[];
    float* Ws = sm + WS_OFF;
    float* Hs = sm + HS_OFF;
    float* Gp = sm + GP_OFF;
    float* Gb = sm + GB_OFF;
    float* Cs = sm + CS_OFF;

    const int tid = threadIdx.x;
    const int nb  = blockIdx.x;            // 0..127

    // ---- load W slice: 32 gate rows x 1024 k, into Ws[k][col] ----
    {
        const int col   = tid >> 3;        // 0..31
        const int lane8 = tid & 7;         // 0..7
        const int grow  = (col >> 3) * HH + nb * 8 + (col & 7);
        const float* wr = Whh + (size_t)grow * HH;
        for (int kb = 0; kb < II; kb += 32) {
            const int k = kb + lane8 * 4;
            float4 v = *(const float4*)(wr + k);
            Ws[(k + 0) * 32 + col] = v.x;
            Ws[(k + 1) * 32 + col] = v.y;
            Ws[(k + 2) * 32 + col] = v.z;
            Ws[(k + 3) * 32 + col] = v.w;
        }
    }
    // ---- load c0 slice into Cs ----
    #pragma unroll
    for (int r = 0; r < 2; r++) {
        const int e = tid + r * 256;
        const int b = e >> 3, j = e & 7;
        Cs[e] = c0[(size_t)b * HH + nb * 8 + j];
    }
    __syncthreads();

    const int grp = tid >> 7;              // split-K group (0/1)
    const int t7  = tid & 127;
    const int tx  = t7 & 7;                // cols tx*4..tx*4+3
    const int ty  = t7 >> 3;               // batches ty*4..ty*4+3
    float* hsg = Hs + grp * HS_G;

    // staging address components (fixed per thread)
    int st_b[8], st_g[8], st_kq[8];
    #pragma unroll
    for (int r = 0; r < 8; r++) {
        const int id = tid + r * 256;
        st_b[r]  = id >> 5;
        st_g[r]  = (id & 31) >> 4;
        st_kq[r] = id & 15;
    }

    for (int t = 0; t < TT; t++) {
        const float* h_in = (t == 0) ? h0 : out + (size_t)(t - 1) * BB * HH;
        const float* xgt  = xg + (size_t)t * BB * G4;
        float* out_t      = out + (size_t)t * BB * HH;

        // ---- prefetch this step's xg slice (DRAM latency hidden) ----
        float4 xv[4];
        if (grp == 0) {
            const int sect = tx >> 1;
            const int jj0  = (tx & 1) * 4;
            #pragma unroll
            for (int i = 0; i < 4; i++)
                xv[i] = __ldg((const float4*)(xgt + (size_t)(ty * 4 + i) * G4
                              + sect * HH + nb * 8 + jj0));
        }

        // ---- prefetch chunk 0 of h ----
        float4 pv[8];
        #pragma unroll
        for (int r = 0; r < 8; r++)
            pv[r] = __ldcg((const float4*)(h_in + (size_t)st_b[r] * HH
                           + st_g[r] * 512 + st_kq[r] * 4));

        ull acc[4][2];
        #pragma unroll
        for (int i = 0; i < 4; i++) { acc[i][0] = 0ull; acc[i][1] = 0ull; }

        for (int ch = 0; ch < 8; ch++) {
            // store prefetched chunk into Hs (bank-rotated scatter)
            #pragma unroll
            for (int r = 0; r < 8; r++) {
                float vv[4] = {pv[r].x, pv[r].y, pv[r].z, pv[r].w};
                float* hd = Hs + st_g[r] * HS_G;
                #pragma unroll
                for (int jj = 0; jj < 4; jj++) {
                    const int e = (jj + st_kq[r]) & 3;
                    hd[(st_kq[r] * 4 + e) * 68 + st_b[r]] = vv[e];
                }
            }
            __syncthreads();

            // prefetch next chunk (overlaps the fma loop below)
            if (ch < 7) {
                #pragma unroll
                for (int r = 0; r < 8; r++)
                    pv[r] = __ldcg((const float4*)(h_in + (size_t)st_b[r] * HH
                                   + st_g[r] * 512 + (ch + 1) * 64 + st_kq[r] * 4));
            }

            const int kbase = grp * 512 + ch * 64;
            #pragma unroll 4
            for (int kk = 0; kk < 64; kk++) {
                const float4 hv = *(const float4*)&hsg[kk * 68 + ty * 4];
                const ulonglong2 wv = *(const ulonglong2*)&Ws[(kbase + kk) * 32 + tx * 4];
                const ull a0 = pack2(hv.x), a1 = pack2(hv.y);
                const ull a2 = pack2(hv.z), a3 = pack2(hv.w);
                fma2(acc[0][0], a0, wv.x); fma2(acc[0][1], a0, wv.y);
                fma2(acc[1][0], a1, wv.x); fma2(acc[1][1], a1, wv.y);
                fma2(acc[2][0], a2, wv.x); fma2(acc[2][1], a2, wv.y);
                fma2(acc[3][0], a3, wv.x); fma2(acc[3][1], a3, wv.y);
            }
            __syncthreads();
        }

        // ---- split-K reduction ----
        if (grp == 1) {
            #pragma unroll
            for (int i = 0; i < 4; i++) {
                const int b = ty * 4 + i;
                float2 p0 = unpack2(acc[i][0]);
                float2 p1 = unpack2(acc[i][1]);
                Gp[b * 33 + tx * 4 + 0] = p0.x;
                Gp[b * 33 + tx * 4 + 1] = p0.y;
                Gp[b * 33 + tx * 4 + 2] = p1.x;
                Gp[b * 33 + tx * 4 + 3] = p1.y;
            }
        }
        __syncthreads();
        if (grp == 0) {
            #pragma unroll
            for (int i = 0; i < 4; i++) {
                const int b = ty * 4 + i;
                float2 p0 = unpack2(acc[i][0]);
                float2 p1 = unpack2(acc[i][1]);
                Gb[b * 33 + tx * 4 + 0] = p0.x + Gp[b * 33 + tx * 4 + 0] + xv[i].x;
                Gb[b * 33 + tx * 4 + 1] = p0.y + Gp[b * 33 + tx * 4 + 1] + xv[i].y;
                Gb[b * 33 + tx * 4 + 2] = p1.x + Gp[b * 33 + tx * 4 + 2] + xv[i].z;
                Gb[b * 33 + tx * 4 + 3] = p1.y + Gp[b * 33 + tx * 4 + 3] + xv[i].w;
            }
        }
        __syncthreads();

        // ---- fused pointwise LSTM update ----
        #pragma unroll
        for (int r = 0; r < 2; r++) {
            const int e = tid + r * 256;
            const int b = e >> 3, j = e & 7;
            const float ig = Gb[b * 33 + j];
            const float fg = Gb[b * 33 + 8 + j];
            const float gg = Gb[b * 33 + 16 + j];
            const float og = Gb[b * 33 + 24 + j];
            const float si = 1.0f / (1.0f + expf(-ig));
            const float sf = 1.0f / (1.0f + expf(-fg));
            const float so = 1.0f / (1.0f + expf(-og));
            const float tg = tanhf(gg);
            const float cn = sf * Cs[e] + si * tg;
            const float hn = so * tanhf(cn);
            Cs[e] = cn;
            const int hc = nb * 8 + j;
            __stcg(out_t + (size_t)b * HH + hc, hn);
            if (t == TT - 1) {
                hf[(size_t)b * HH + hc] = hn;
                cf[(size_t)b * HH + hc] = cn;
            }
        }

        // ---- grid-wide barrier ----
        __syncthreads();
        if (tid == 0) {
            __threadfence();
            const unsigned target = (unsigned)(t + 1) * GRID;
            atomicAdd(&g_bar, 1u);
            while (*(volatile unsigned*)&g_bar < target) { __nanosleep(64); }
            __threadfence();
        }
        __syncthreads();
    }
}

// ---------------------------------------------------------------------------
extern "C" void kernel_launch(void* const* d_in, const int* in_sizes, int n_in,
                              void* d_out, int out_size)
{
    const float* input = (const float*)d_in[0];
    const float* h0    = (const float*)d_in[1];
    const float* c0    = (const float*)d_in[2];
    const float* w_ih  = (const float*)d_in[3];
    const float* w_hh  = (const float*)d_in[4];
    const float* b_ih  = (const float*)d_in[5];
    const float* b_hh  = (const float*)d_in[6];

    float* outputs = (float*)d_out;                 // [T, B, H]
    float* hf = outputs + (size_t)TT * BB * HH;
    float* cf = hf + (size_t)BB * HH;

    float* xg = nullptr;
    cudaGetSymbolAddress((void**)&xg, g_xg);

    const size_t smem_bytes = (size_t)SMEM_FLOATS * sizeof(float);
    cudaFuncSetAttribute(lstm_persist,
                         cudaFuncAttributeMaxDynamicSharedMemorySize,
                         (int)smem_bytes);

    bar_reset<<<1, 1>>>();

    dim3 blk(16, 16);
    gemm_xgates<<<dim3(G4 / 64, (TT * BB) / 64), blk>>>(input, w_ih, b_ih, b_hh, xg);

    lstm_persist<<<GRID, 256, smem_bytes>>>(xg, h0, c0, w_hh, outputs, hf, cf);
}